// round 7
// baseline (speedup 1.0000x reference)
#include <cuda_runtime.h>
#include <cuda_bf16.h>
#include <cstdint>

// Problem constants
#define N_NODES 100000
#define N_EDGES 1600000
#define IN_DIM  512
#define HID_DIM 128
#define OUT_DIM 64

// ---------------------------------------------------------------------------
// Scratch (static __device__ globals). NEVER passed as kernel arguments from
// host code (host-side symbol decay gives the host shadow address, which on
// GB300/ATS is silently dereferenceable -> wrong memory). All access to these
// happens from device code.
// ---------------------------------------------------------------------------
__device__ __align__(16) float g_support[(size_t)N_NODES * HID_DIM];
__device__ __align__(16) float g_h[(size_t)N_NODES * HID_DIM];
__device__ __align__(16) float g_hw[(size_t)N_NODES * OUT_DIM];
__device__ int   g_rowptr[N_NODES + 1];
__device__ int   g_cursor[N_NODES];
__device__ int   g_cols[N_EDGES];
__device__ float g_vals[N_EDGES];
__device__ int   g_bsums[64];
__device__ int   g_inrange[3];
__device__ const int*   g_erow_p;
__device__ const int*   g_ecol_p;
__device__ const float* g_evals_p;

// ---------------------------------------------------------------------------
// Input classification: identify which of the three E-sized arrays is the
// float edge_vals (int-in-range fraction ~0) vs the two int index arrays
// (fraction ~1). Sampled: every 64th element.
// ---------------------------------------------------------------------------
#define CLS_SAMPLES (N_EDGES / 64)   // 25000

__global__ void zero_misc_kernel() {
    int i = blockIdx.x * blockDim.x + threadIdx.x;
    if (i <= N_NODES) g_rowptr[i] = 0;
    if (i < 3) g_inrange[i] = 0;
}

__global__ void classify_kernel(const int* __restrict__ a0,
                                const int* __restrict__ a1,
                                const int* __restrict__ a2) {
    __shared__ int s[3];
    if (threadIdx.x < 3) s[threadIdx.x] = 0;
    __syncthreads();
    int i = blockIdx.x * blockDim.x + threadIdx.x;
    if (i < CLS_SAMPLES) {
        int idx = i * 64;
        if ((unsigned)__ldg(a0 + idx) < (unsigned)N_NODES) atomicAdd(&s[0], 1);
        if ((unsigned)__ldg(a1 + idx) < (unsigned)N_NODES) atomicAdd(&s[1], 1);
        if ((unsigned)__ldg(a2 + idx) < (unsigned)N_NODES) atomicAdd(&s[2], 1);
    }
    __syncthreads();
    if (threadIdx.x < 3) atomicAdd(&g_inrange[threadIdx.x], s[threadIdx.x]);
}

// 1 thread: vals = array with the LOWEST in-range count; the two index arrays,
// kept in metadata order, are (edge_row, edge_col).
__global__ void select_kernel(const int* a0, const int* a1, const int* a2) {
    int c0 = g_inrange[0], c1 = g_inrange[1], c2 = g_inrange[2];
    int vi = (c0 <= c1 && c0 <= c2) ? 0 : ((c1 <= c2) ? 1 : 2);
    const int* arr[3] = {a0, a1, a2};
    int o0 = (vi == 0) ? 1 : 0;           // first remaining index
    int o1 = (vi == 2) ? 1 : 2;           // second remaining index
    g_erow_p  = arr[o0];                  // metadata order: row before col
    g_ecol_p  = arr[o1];
    g_evals_p = (const float*)arr[vi];
}

// ---------------------------------------------------------------------------
// CSR build
// ---------------------------------------------------------------------------
__global__ void hist_kernel() {
    const int* __restrict__ erow = g_erow_p;
    int i = blockIdx.x * blockDim.x + threadIdx.x;
    if (i < N_EDGES) {
        unsigned r = (unsigned)__ldg(erow + i);
        if (r < (unsigned)N_NODES)
            atomicAdd(&g_rowptr[r + 1], 1);
    }
}

// inclusive scan pass 1: 2048 elems per block (256 thr x 8)
__global__ void scan_partial_kernel() {
    const int TPB = 256, ITEMS = 8, PER = TPB * ITEMS;
    const int L = N_NODES + 1;
    __shared__ int s[TPB];
    int base = blockIdx.x * PER + threadIdx.x * ITEMS;
    int v[ITEMS];
    int running = 0;
#pragma unroll
    for (int i = 0; i < ITEMS; i++) {
        int x = (base + i < L) ? g_rowptr[base + i] : 0;
        running += x;
        v[i] = running;
    }
    s[threadIdx.x] = running;
    __syncthreads();
    for (int off = 1; off < TPB; off <<= 1) {
        int t = (threadIdx.x >= off) ? s[threadIdx.x - off] : 0;
        __syncthreads();
        s[threadIdx.x] += t;
        __syncthreads();
    }
    int excl = s[threadIdx.x] - running;
#pragma unroll
    for (int i = 0; i < ITEMS; i++)
        if (base + i < L) g_rowptr[base + i] = v[i] + excl;
    if (threadIdx.x == TPB - 1) g_bsums[blockIdx.x] = s[TPB - 1];
}

__global__ void scan_sums_kernel(int nb) {
    if (threadIdx.x == 0 && blockIdx.x == 0) {
        int acc = 0;
        for (int i = 0; i < nb; i++) {
            int t = g_bsums[i];
            g_bsums[i] = acc;
            acc += t;
        }
    }
}

__global__ void scan_add_kernel() {
    const int L = N_NODES + 1;
    int i = blockIdx.x * blockDim.x + threadIdx.x;
    if (i < L) {
        int v = g_rowptr[i] + g_bsums[i / 2048];
        g_rowptr[i] = v;
        if (i < N_NODES) g_cursor[i] = v;
    }
}

__global__ void scatter_kernel() {
    const int*   __restrict__ erow  = g_erow_p;
    const int*   __restrict__ ecol  = g_ecol_p;
    const float* __restrict__ evals = g_evals_p;
    int i = blockIdx.x * blockDim.x + threadIdx.x;
    if (i < N_EDGES) {
        unsigned r = (unsigned)__ldg(erow + i);
        if (r >= (unsigned)N_NODES) return;
        unsigned c = (unsigned)__ldg(ecol + i);
        if (c >= (unsigned)N_NODES) c = N_NODES - 1;
        int p = atomicAdd(&g_cursor[r], 1);
        g_cols[p] = (int)c;
        g_vals[p] = __ldg(evals + i);
    }
}

// ---------------------------------------------------------------------------
// Tiled fp32 GEMM: C[M,N] = A[M,K] @ B[K,N]
//   LAYER 1: A=feature (arg), C=g_support.  LAYER 2: A=g_h, C=g_hw.
//   Scratch pointers resolved in DEVICE code.
// ---------------------------------------------------------------------------
template <int LAYER, int BM, int BN, int BK, int TM, int TN, int K, int N>
__global__ __launch_bounds__(256)
void gemm_kernel(const float* __restrict__ A_in, const float* __restrict__ B,
                 int M) {
    const float* __restrict__ A = (LAYER == 1) ? A_in : (const float*)g_h;
    float* __restrict__ C = (LAYER == 1) ? (float*)g_support : (float*)g_hw;

    constexpr int THREADS = (BM / TM) * (BN / TN);
    static_assert(THREADS == 256, "expect 256 threads");
    constexpr int ASTRIDE = BM + 4;

    __shared__ float As[BK][ASTRIDE];
    __shared__ float Bs[BK][BN];

    const int tid = threadIdx.x;
    const int nGroups = BN / TN;           // 32
    const int n_idx = tid % nGroups;
    const int m_idx = tid / nGroups;       // 0..7
    const int row0 = blockIdx.x * BM;

    float acc[TM][TN];
#pragma unroll
    for (int i = 0; i < TM; i++)
#pragma unroll
        for (int j = 0; j < TN; j++) acc[i][j] = 0.f;

    for (int k0 = 0; k0 < K; k0 += BK) {
        constexpr int A4 = BM * BK / 4;
#pragma unroll
        for (int i = tid; i < A4; i += THREADS) {
            int r  = i / (BK / 4);
            int c4 = (i % (BK / 4)) * 4;
            float4 v = make_float4(0.f, 0.f, 0.f, 0.f);
            int gr = row0 + r;
            if (gr < M)
                v = *reinterpret_cast<const float4*>(A + (size_t)gr * K + k0 + c4);
            As[c4 + 0][r] = v.x;
            As[c4 + 1][r] = v.y;
            As[c4 + 2][r] = v.z;
            As[c4 + 3][r] = v.w;
        }
        constexpr int B4 = BK * BN / 4;
#pragma unroll
        for (int i = tid; i < B4; i += THREADS) {
            int r  = i / (BN / 4);
            int c4 = (i % (BN / 4)) * 4;
            *reinterpret_cast<float4*>(&Bs[r][c4]) =
                *reinterpret_cast<const float4*>(B + (size_t)(k0 + r) * N + c4);
        }
        __syncthreads();

#pragma unroll
        for (int kk = 0; kk < BK; kk++) {
            float a[TM];
            *reinterpret_cast<float4*>(&a[0]) =
                *reinterpret_cast<const float4*>(&As[kk][m_idx * TM]);
            *reinterpret_cast<float4*>(&a[4]) =
                *reinterpret_cast<const float4*>(&As[kk][m_idx * TM + 4]);
            float b[TN];
            if constexpr (TN == 4) {
                *reinterpret_cast<float4*>(&b[0]) =
                    *reinterpret_cast<const float4*>(&Bs[kk][n_idx * TN]);
            } else {
                *reinterpret_cast<float2*>(&b[0]) =
                    *reinterpret_cast<const float2*>(&Bs[kk][n_idx * TN]);
            }
#pragma unroll
            for (int i = 0; i < TM; i++)
#pragma unroll
                for (int j = 0; j < TN; j++)
                    acc[i][j] = fmaf(a[i], b[j], acc[i][j]);
        }
        __syncthreads();
    }

#pragma unroll
    for (int i = 0; i < TM; i++) {
        int gr = row0 + m_idx * TM + i;
        if (gr < M) {
            if constexpr (TN == 4) {
                float4 v = make_float4(acc[i][0], acc[i][1], acc[i][2], acc[i][3]);
                *reinterpret_cast<float4*>(C + (size_t)gr * N + n_idx * TN) = v;
            } else {
                float2 v = make_float2(acc[i][0], acc[i][1]);
                *reinterpret_cast<float2*>(C + (size_t)gr * N + n_idx * TN) = v;
            }
        }
    }
}

// ---------------------------------------------------------------------------
// SpMM: out[r,:] = sum_{e in row r} val[e] * dense[col[e],:]
// warp per row; LAYER 1: dense=g_support -> g_h (relu); LAYER 2: g_hw -> out.
// ---------------------------------------------------------------------------
template <int LAYER>
__global__ __launch_bounds__(256)
void spmm_kernel(float* __restrict__ out_arg) {
    constexpr int D = (LAYER == 1) ? HID_DIM : OUT_DIM;
    constexpr int V = D / 32;  // 4 or 2
    const float* __restrict__ dense = (LAYER == 1) ? (const float*)g_support
                                                   : (const float*)g_hw;
    float* __restrict__ out = (LAYER == 1) ? (float*)g_h : out_arg;

    int row  = (blockIdx.x * blockDim.x + threadIdx.x) >> 5;
    int lane = threadIdx.x & 31;
    if (row >= N_NODES) return;

    int s = g_rowptr[row];
    int e = g_rowptr[row + 1];

    float acc[V];
#pragma unroll
    for (int j = 0; j < V; j++) acc[j] = 0.f;

    int i = s;
    for (; i + 1 < e; i += 2) {
        int   c0 = __ldg(&g_cols[i]);
        int   c1 = __ldg(&g_cols[i + 1]);
        float v0 = __ldg(&g_vals[i]);
        float v1 = __ldg(&g_vals[i + 1]);
        if constexpr (V == 4) {
            float4 d0 = __ldg(reinterpret_cast<const float4*>(dense + (size_t)c0 * D + lane * 4));
            float4 d1 = __ldg(reinterpret_cast<const float4*>(dense + (size_t)c1 * D + lane * 4));
            acc[0] = fmaf(v0, d0.x, acc[0]); acc[1] = fmaf(v0, d0.y, acc[1]);
            acc[2] = fmaf(v0, d0.z, acc[2]); acc[3] = fmaf(v0, d0.w, acc[3]);
            acc[0] = fmaf(v1, d1.x, acc[0]); acc[1] = fmaf(v1, d1.y, acc[1]);
            acc[2] = fmaf(v1, d1.z, acc[2]); acc[3] = fmaf(v1, d1.w, acc[3]);
        } else {
            float2 d0 = __ldg(reinterpret_cast<const float2*>(dense + (size_t)c0 * D + lane * 2));
            float2 d1 = __ldg(reinterpret_cast<const float2*>(dense + (size_t)c1 * D + lane * 2));
            acc[0] = fmaf(v0, d0.x, acc[0]); acc[1] = fmaf(v0, d0.y, acc[1]);
            acc[0] = fmaf(v1, d1.x, acc[0]); acc[1] = fmaf(v1, d1.y, acc[1]);
        }
    }
    if (i < e) {
        int   c0 = __ldg(&g_cols[i]);
        float v0 = __ldg(&g_vals[i]);
        if constexpr (V == 4) {
            float4 d0 = __ldg(reinterpret_cast<const float4*>(dense + (size_t)c0 * D + lane * 4));
            acc[0] = fmaf(v0, d0.x, acc[0]); acc[1] = fmaf(v0, d0.y, acc[1]);
            acc[2] = fmaf(v0, d0.z, acc[2]); acc[3] = fmaf(v0, d0.w, acc[3]);
        } else {
            float2 d0 = __ldg(reinterpret_cast<const float2*>(dense + (size_t)c0 * D + lane * 2));
            acc[0] = fmaf(v0, d0.x, acc[0]); acc[1] = fmaf(v0, d0.y, acc[1]);
        }
    }

    if constexpr (LAYER == 1) {
#pragma unroll
        for (int j = 0; j < V; j++) acc[j] = fmaxf(acc[j], 0.f);
    }

    if constexpr (V == 4) {
        float4 v = make_float4(acc[0], acc[1], acc[2], acc[3]);
        *reinterpret_cast<float4*>(out + (size_t)row * D + lane * 4) = v;
    } else {
        float2 v = make_float2(acc[0], acc[1]);
        *reinterpret_cast<float2*>(out + (size_t)row * D + lane * 2) = v;
    }
}

// ---------------------------------------------------------------------------
// Launch. Unique-size inputs identified by element count; the three E-sized
// arrays are classified ON DEVICE (vals = non-index-like), row/col taken in
// metadata order.
// ---------------------------------------------------------------------------
extern "C" void kernel_launch(void* const* d_in, const int* in_sizes, int n_in,
                              void* d_out, int out_size) {
    const float* feature = nullptr;
    const float* W1 = nullptr;
    const float* W2 = nullptr;
    const int*   e_arr[3] = {nullptr, nullptr, nullptr};
    int e_seen = 0;

    for (int i = 0; i < n_in; i++) {
        long sz = in_sizes[i];
        if (sz == (long)N_NODES * IN_DIM)       feature = (const float*)d_in[i];
        else if (sz == (long)IN_DIM * HID_DIM)  W1 = (const float*)d_in[i];
        else if (sz == (long)HID_DIM * OUT_DIM) W2 = (const float*)d_in[i];
        else if (sz == (long)N_EDGES) { if (e_seen < 3) e_arr[e_seen++] = (const int*)d_in[i]; }
    }
    float* out = (float*)d_out;

    const int L = N_NODES + 1;
    const int SCAN_NB = (L + 2047) / 2048;  // 49

    // classify + CSR build
    zero_misc_kernel<<<(L + 255) / 256, 256>>>();
    classify_kernel<<<(CLS_SAMPLES + 255) / 256, 256>>>(e_arr[0], e_arr[1], e_arr[2]);
    select_kernel<<<1, 1>>>(e_arr[0], e_arr[1], e_arr[2]);
    hist_kernel<<<(N_EDGES + 255) / 256, 256>>>();
    scan_partial_kernel<<<SCAN_NB, 256>>>();
    scan_sums_kernel<<<1, 32>>>(SCAN_NB);
    scan_add_kernel<<<(L + 255) / 256, 256>>>();
    scatter_kernel<<<(N_EDGES + 255) / 256, 256>>>();

    // layer 1: support = X @ W1 ; h = relu(A @ support)
    gemm_kernel<1, 64, 128, 32, 8, 4, IN_DIM, HID_DIM>
        <<<(N_NODES + 63) / 64, 256>>>(feature, W1, N_NODES);
    spmm_kernel<1><<<(N_NODES * 32 + 255) / 256, 256>>>(nullptr);

    // layer 2: hw = h @ W2 ; logits = A @ hw
    gemm_kernel<2, 64, 64, 32, 8, 2, HID_DIM, OUT_DIM>
        <<<(N_NODES + 63) / 64, 256>>>(nullptr, W2, N_NODES);
    spmm_kernel<2><<<(N_NODES * 32 + 255) / 256, 256>>>(out);
}